// round 10
// baseline (speedup 1.0000x reference)
#include <cuda_runtime.h>
#include <math.h>

#define TILE_W    112
#define TILE_H    8
#define HALO      5
#define RAW_W     (TILE_W + 2*HALO)   /* 122 columns incl. halo */
#define VP        123                 /* vs pitch in 16B pairs (mod 8 = 3, odd) */
#define NTHREADS  256
#define NGROUPS   (TILE_H / 4)        /* 2 row groups of 4 */
#define VITEMS    (RAW_W * NGROUPS)   /* 244 */
#define HITEMS    (TILE_H * (TILE_W/4)) /* 224 */

typedef unsigned long long u64;

// Per-block partial sums (deterministic: each block writes exactly one slot).
__device__ float g_blockSums[65536];
__device__ unsigned int g_count = 0;

// Normalized 1D Gaussian, size 11, sigma 1.5 (matches cv2.getGaussianKernel).
__device__ __forceinline__ float gw(int t) {
    constexpr float G[11] = {
        0.00102838f, 0.00759876f, 0.03600077f, 0.10936069f, 0.21300553f,
        0.26601172f,
        0.21300553f, 0.10936069f, 0.03600077f, 0.00759876f, 0.00102838f };
    return G[t];
}
__device__ __forceinline__ int wux(int t) { return t <= 5 ? t : 10 - t; }

// packed duplicated weights in constant memory (keeps them out of registers)
__constant__ float2 cGW2[6] = {
    {0.00102838f, 0.00102838f}, {0.00759876f, 0.00759876f},
    {0.03600077f, 0.03600077f}, {0.10936069f, 0.10936069f},
    {0.21300553f, 0.21300553f}, {0.26601172f, 0.26601172f} };

__device__ __forceinline__ u64 ldw2(int t) {
    return *reinterpret_cast<const u64*>(&cGW2[wux(t)]);
}

// ---- packed f32x2 helpers (Blackwell) ----
__device__ __forceinline__ u64 pack2(float lo, float hi) {
    u64 r; asm("mov.b64 %0, {%1, %2};" : "=l"(r) : "f"(lo), "f"(hi)); return r;
}
__device__ __forceinline__ void unpack2(u64 v, float& lo, float& hi) {
    asm("mov.b64 {%0, %1}, %2;" : "=f"(lo), "=f"(hi) : "l"(v));
}
__device__ __forceinline__ u64 mul2(u64 a, u64 b) {
    u64 d; asm("mul.rn.f32x2 %0, %1, %2;" : "=l"(d) : "l"(a), "l"(b)); return d;
}
__device__ __forceinline__ u64 fma2(u64 a, u64 b, u64 c) {
    u64 d; asm("fma.rn.f32x2 %0, %1, %2, %3;" : "=l"(d) : "l"(a), "l"(b), "l"(c)); return d;
}

// Vertical 11-tap blur for one (column, 4-row-group) item, reading gmem directly.
// Writes packed ((G(x),G(y)),(G(xx+yy),G(xy))) into vs.
template<bool CLAMP>
__device__ __forceinline__ void vitem(const float* __restrict__ img1,
                                      const float* __restrict__ img2,
                                      int W, int H, int bx, int by, int item,
                                      u64 (*vs)[VP][2])
{
    const int grp = (item >= RAW_W) ? 1 : 0;
    const int col = item - grp * RAW_W;
    const int r0  = grp * 4;             // output rows r0..r0+3 (tile-local)

    u64 vmu[4] = {0ull, 0ull, 0ull, 0ull};
    u64 vsp[4] = {0ull, 0ull, 0ull, 0ull};

    int gx = bx - HALO + col;
    if (CLAMP) gx = min(max(gx, 0), W - 1);

    const float* __restrict__ p1;
    const float* __restrict__ p2;
    if (!CLAMP) {
        const size_t base = (size_t)(by + r0 - HALO) * (size_t)W + (size_t)gx;
        p1 = img1 + base;
        p2 = img2 + base;
    }

    #pragma unroll
    for (int j = 0; j < 14; j++) {
        float x, y;
        if (CLAMP) {
            int gy = by + r0 - HALO + j;
            gy = min(max(gy, 0), H - 1);
            const size_t idx = (size_t)gy * (size_t)W + (size_t)gx;
            x = __ldg(img1 + idx);
            y = __ldg(img2 + idx);
        } else {
            x = __ldg(p1);
            y = __ldg(p2);
            p1 += W;
            p2 += W;
        }
        const u64 v2 = pack2(x, y);
        const float ss = fmaf(x, x, y * y);    // x^2 + y^2
        const float xy = x * y;
        const u64 p2v = pack2(ss, xy);
        #pragma unroll
        for (int o = 0; o < 4; o++) {
            const int t = j - o;
            if (t >= 0 && t < 11) {
                const u64 w2 = ldw2(t);
                vmu[o] = fma2(v2,  w2, vmu[o]);
                vsp[o] = fma2(p2v, w2, vsp[o]);
            }
        }
    }
    #pragma unroll
    for (int o = 0; o < 4; o++) {
        ulonglong2* dst = reinterpret_cast<ulonglong2*>(&vs[r0 + o][col][0]);
        *dst = make_ulonglong2(vmu[o], vsp[o]);    // STS.128
    }
}

__global__ __launch_bounds__(NTHREADS, 6)
void ssim_tile_kernel(const float* __restrict__ img1,
                      const float* __restrict__ img2,
                      int W, int H, int nBlocks, double inv_n,
                      float* __restrict__ out)
{
    __shared__ u64   vs[TILE_H][VP][2];   // vertical-blurred, packed 16B/px
    __shared__ float wsum[NTHREADS / 32];
    __shared__ bool  isLast;

    const int tid = threadIdx.x;
    const int bx = blockIdx.x * TILE_W;
    const int by = blockIdx.y * TILE_H;

    // ---------------- vertical pass from gmem: 122 cols x 2 row-groups = 244 items ----
    const bool interior = (bx >= HALO) && (by >= HALO) &&
                          (bx + TILE_W + HALO <= W) && (by + TILE_H + HALO <= H);
    if (tid < VITEMS) {
        if (interior) vitem<false>(img1, img2, W, H, bx, by, tid, vs);
        else          vitem<true >(img1, img2, W, H, bx, by, tid, vs);
    }
    __syncthreads();

    // ---------------- horizontal pass + SSIM: 8 rows x 28 groups of 4 cols ----------
    // Lane map: r=tid&7 (pitch 123, 123*r mod 8 distinct) -> conflict-free LDS.128.
    float lsum = 0.f;
    if (tid < HITEMS) {
        const int r  = tid & 7;
        const int g4 = (tid >> 3) << 2;   // output cols g4..g4+3

        u64 hmu[4] = {0ull, 0ull, 0ull, 0ull};
        u64 hsp[4] = {0ull, 0ull, 0ull, 0ull};

        #pragma unroll
        for (int k = 0; k < 14; k++) {
            const ulonglong2 v =
                *reinterpret_cast<const ulonglong2*>(&vs[r][g4 + k][0]);  // LDS.128
            const u64 m = v.x;
            const u64 s = v.y;
            #pragma unroll
            for (int o = 0; o < 4; o++) {
                const int t = k - o;
                if (t >= 0 && t < 11) {
                    const u64 w2 = ldw2(t);
                    hmu[o] = fma2(m, w2, hmu[o]);
                    hsp[o] = fma2(s, w2, hsp[o]);
                }
            }
        }

        // Folded constants: everything scaled by SCALE = 2^-12 exactly once per
        // factor, so nn and dd are both (orig * SCALE^2) -> ratio unchanged.
        const float SCALE = 0.000244140625f;          // 2^-12
        const float TWOS  = 2.0f * SCALE;             // 2*2^-12 (exact)
        const float C1S   = 6.5025f  * 0.000244140625f;
        const float C2S   = 58.5225f * 0.000244140625f;

        float nn[4], dd[4];
        #pragma unroll
        for (int o = 0; o < 4; o++) {
            const bool valid = interior || (by + r < H && bx + g4 + o < W);
            if (valid) {
                float m11, m22, mu1, mu2, sqs, exy;
                const u64 mm = mul2(hmu[o], hmu[o]);   // (mu1^2, mu2^2) packed
                unpack2(mm, m11, m22);
                unpack2(hmu[o], mu1, mu2);
                unpack2(hsp[o], sqs, exy);    // sqs = G(xx)+G(yy), exy = G(xy)
                const float m12  = mu1 * mu2;
                const float msum = m11 + m22;
                const float f1 = fmaf(m12, TWOS, C1S);          // S*(2*m12+C1)
                const float f2 = fmaf(exy - m12, TWOS, C2S);    // S*(2*s12+C2)
                const float f3 = fmaf(msum, SCALE, C1S);        // S*(msum+C1)
                const float f4 = fmaf(sqs - msum, SCALE, C2S);  // S*(ssum+C2)
                nn[o] = f1 * f2;
                dd[o] = f3 * f4;
            } else {
                nn[o] = 0.f;
                dd[o] = 1.f;
            }
        }
        // sum_i n_i/d_i = (sum_i n_i * prod_{j!=i} d_j) / prod_j d_j -> one RCP / 4 px
        const float d01 = dd[0] * dd[1];
        const float d23 = dd[2] * dd[3];
        const float D   = d01 * d23;
        const float s01 = fmaf(nn[0], dd[1], nn[1] * dd[0]);
        const float s23 = fmaf(nn[2], dd[3], nn[3] * dd[2]);
        const float S   = fmaf(s01, d23, s23 * d01);
        lsum = __fdividef(S, D);
    }

    // ---------------- block reduction ----------------
    #pragma unroll
    for (int off = 16; off; off >>= 1)
        lsum += __shfl_xor_sync(0xffffffffu, lsum, off);
    if ((tid & 31) == 0) wsum[tid >> 5] = lsum;
    __syncthreads();
    if (tid == 0) {
        float s = 0.f;
        #pragma unroll
        for (int w = 0; w < NTHREADS / 32; w++) s += wsum[w];
        g_blockSums[blockIdx.y * gridDim.x + blockIdx.x] = s;
        __threadfence();
        unsigned int prev = atomicAdd(&g_count, 1u);
        isLast = (prev == (unsigned int)(nBlocks - 1));
    }
    __syncthreads();

    // ---------------- last block: final deterministic reduce ----------------
    if (isLast) {
        // reuse vs storage for the double scratch (all vs uses are done)
        double* dsm = reinterpret_cast<double*>(&vs[0][0][0]);
        double acc = 0.0;
        if ((nBlocks & 3) == 0) {
            const float4* p = (const float4*)g_blockSums;
            const int n4 = nBlocks >> 2;
            for (int i = tid; i < n4; i += NTHREADS) {
                float4 v = p[i];
                acc += (double)v.x + (double)v.y + (double)v.z + (double)v.w;
            }
        } else {
            for (int i = tid; i < nBlocks; i += NTHREADS)
                acc += (double)g_blockSums[i];
        }
        dsm[tid] = acc;
        __syncthreads();
        #pragma unroll
        for (int s = NTHREADS / 2; s; s >>= 1) {
            if (tid < s) dsm[tid] += dsm[tid + s];
            __syncthreads();
        }
        if (tid == 0) {
            out[0] = (float)(dsm[0] * inv_n);
            g_count = 0;   // reset for next graph replay (deterministic)
        }
    }
}

extern "C" void kernel_launch(void* const* d_in, const int* in_sizes, int n_in,
                              void* d_out, int out_size)
{
    (void)n_in; (void)out_size;
    const float* img1 = (const float*)d_in[0];
    const float* img2 = (const float*)d_in[1];

    const long long n = (long long)in_sizes[0];
    int W = (int)(sqrt((double)n) + 0.5);
    if (W <= 0) W = 1;
    int H = (int)(n / W);

    dim3 grid((W + TILE_W - 1) / TILE_W, (H + TILE_H - 1) / TILE_H);
    const int nb = (int)(grid.x * grid.y);
    const double inv_n = 1.0 / ((double)H * (double)W);
    ssim_tile_kernel<<<grid, NTHREADS>>>(img1, img2, W, H, nb, inv_n,
                                         (float*)d_out);
}

// round 11
// speedup vs baseline: 1.0624x; 1.0624x over previous
#include <cuda_runtime.h>
#include <math.h>

#define TILE_W    112
#define TILE_H    8
#define HALO      5
#define RAW_W     (TILE_W + 2*HALO)   /* 122 columns incl. halo */
#define VP        123                 /* vs pitch in 16B pairs (mod 8 = 3, odd) */
#define NTHREADS  256
#define NGROUPS   (TILE_H / 4)        /* 2 row groups of 4 */
#define VITEMS    (RAW_W * NGROUPS)   /* 244 */
#define HITEMS    (TILE_H * (TILE_W/4)) /* 224 */

typedef unsigned long long u64;

// Per-block partial sums (deterministic: each block writes exactly one slot).
__device__ float g_blockSums[65536];
__device__ unsigned int g_count = 0;

// Normalized 1D Gaussian, size 11, sigma 1.5 (matches cv2.getGaussianKernel).
__device__ __forceinline__ float gw(int t) {
    constexpr float G[11] = {
        0.00102838f, 0.00759876f, 0.03600077f, 0.10936069f, 0.21300553f,
        0.26601172f,
        0.21300553f, 0.10936069f, 0.03600077f, 0.00759876f, 0.00102838f };
    return G[t];
}
__device__ __forceinline__ int wux(int t) { return t <= 5 ? t : 10 - t; }

// packed duplicated weights in constant memory (keeps them out of registers)
__constant__ float2 cGW2[6] = {
    {0.00102838f, 0.00102838f}, {0.00759876f, 0.00759876f},
    {0.03600077f, 0.03600077f}, {0.10936069f, 0.10936069f},
    {0.21300553f, 0.21300553f}, {0.26601172f, 0.26601172f} };

// packed epilogue constants (SCALE = 2^-12 folded; ratio unchanged)
__constant__ float2 cNEG1  = {-1.0f, -1.0f};
__constant__ float2 cTWOS  = {4.8828125e-4f, 4.8828125e-4f};   // 2*2^-12
__constant__ float2 cSCL   = {2.44140625e-4f, 2.44140625e-4f}; // 2^-12
__constant__ float2 cC1S   = {1.58752441e-3f, 1.58752441e-3f}; // 6.5025*2^-12
__constant__ float2 cC2S   = {1.42877197e-2f, 1.42877197e-2f}; // 58.5225*2^-12

__device__ __forceinline__ u64 ldw2(int t) {
    return *reinterpret_cast<const u64*>(&cGW2[wux(t)]);
}
__device__ __forceinline__ u64 ldc2(const float2& c) {
    return *reinterpret_cast<const u64*>(&c);
}

// ---- packed f32x2 helpers (Blackwell). pack/unpack are register renames. ----
__device__ __forceinline__ u64 pack2(float lo, float hi) {
    u64 r; asm("mov.b64 %0, {%1, %2};" : "=l"(r) : "f"(lo), "f"(hi)); return r;
}
__device__ __forceinline__ void unpack2(u64 v, float& lo, float& hi) {
    asm("mov.b64 {%0, %1}, %2;" : "=f"(lo), "=f"(hi) : "l"(v));
}
__device__ __forceinline__ u64 mul2(u64 a, u64 b) {
    u64 d; asm("mul.rn.f32x2 %0, %1, %2;" : "=l"(d) : "l"(a), "l"(b)); return d;
}
__device__ __forceinline__ u64 fma2(u64 a, u64 b, u64 c) {
    u64 d; asm("fma.rn.f32x2 %0, %1, %2, %3;" : "=l"(d) : "l"(a), "l"(b), "l"(c)); return d;
}

// Vertical 11-tap blur for one (column, 4-row-group) item, reading gmem directly.
// Writes packed ((G(x),G(y)),(G(xx+yy),G(xy))) into vs.
template<bool CLAMP>
__device__ __forceinline__ void vitem(const float* __restrict__ img1,
                                      const float* __restrict__ img2,
                                      int W, int H, int bx, int by, int item,
                                      u64 (*vs)[VP][2])
{
    const int grp = (item >= RAW_W) ? 1 : 0;
    const int col = item - grp * RAW_W;
    const int r0  = grp * 4;             // output rows r0..r0+3 (tile-local)

    u64 vmu[4] = {0ull, 0ull, 0ull, 0ull};
    u64 vsp[4] = {0ull, 0ull, 0ull, 0ull};

    int gx = bx - HALO + col;
    if (CLAMP) gx = min(max(gx, 0), W - 1);

    const float* __restrict__ p1;
    const float* __restrict__ p2;
    if (!CLAMP) {
        const size_t base = (size_t)(by + r0 - HALO) * (size_t)W + (size_t)gx;
        p1 = img1 + base;
        p2 = img2 + base;
    }

    #pragma unroll
    for (int j = 0; j < 14; j++) {
        float x, y;
        if (CLAMP) {
            int gy = by + r0 - HALO + j;
            gy = min(max(gy, 0), H - 1);
            const size_t idx = (size_t)gy * (size_t)W + (size_t)gx;
            x = __ldg(img1 + idx);
            y = __ldg(img2 + idx);
        } else {
            x = __ldg(p1);
            y = __ldg(p2);
            p1 += W;
            p2 += W;
        }
        const u64 v2 = pack2(x, y);
        const float ss = fmaf(x, x, y * y);    // x^2 + y^2
        const float xy = x * y;
        const u64 p2v = pack2(ss, xy);
        #pragma unroll
        for (int o = 0; o < 4; o++) {
            const int t = j - o;
            if (t >= 0 && t < 11) {
                const u64 w2 = ldw2(t);
                vmu[o] = fma2(v2,  w2, vmu[o]);
                vsp[o] = fma2(p2v, w2, vsp[o]);
            }
        }
    }
    #pragma unroll
    for (int o = 0; o < 4; o++) {
        ulonglong2* dst = reinterpret_cast<ulonglong2*>(&vs[r0 + o][col][0]);
        *dst = make_ulonglong2(vmu[o], vsp[o]);    // STS.128
    }
}

__global__ __launch_bounds__(NTHREADS, 6)
void ssim_tile_kernel(const float* __restrict__ img1,
                      const float* __restrict__ img2,
                      int W, int H, int nBlocks, double inv_n,
                      float* __restrict__ out)
{
    __shared__ u64   vs[TILE_H][VP][2];   // vertical-blurred, packed 16B/px
    __shared__ float wsum[NTHREADS / 32];
    __shared__ bool  isLast;

    const int tid = threadIdx.x;
    const int bx = blockIdx.x * TILE_W;
    const int by = blockIdx.y * TILE_H;

    // ---------------- vertical pass from gmem: 122 cols x 2 row-groups = 244 items ----
    const bool interior = (bx >= HALO) && (by >= HALO) &&
                          (bx + TILE_W + HALO <= W) && (by + TILE_H + HALO <= H);
    if (tid < VITEMS) {
        if (interior) vitem<false>(img1, img2, W, H, bx, by, tid, vs);
        else          vitem<true >(img1, img2, W, H, bx, by, tid, vs);
    }
    __syncthreads();

    // ---------------- horizontal pass + SSIM: 8 rows x 28 groups of 4 cols ----------
    // Lane map: r=tid&7 (pitch 123, 123*r mod 8 distinct) -> conflict-free LDS.128.
    float lsum = 0.f;
    if (tid < HITEMS) {
        const int r  = tid & 7;
        const int g4 = (tid >> 3) << 2;   // output cols g4..g4+3

        u64 hmu[4] = {0ull, 0ull, 0ull, 0ull};
        u64 hsp[4] = {0ull, 0ull, 0ull, 0ull};

        #pragma unroll
        for (int k = 0; k < 14; k++) {
            const ulonglong2 v =
                *reinterpret_cast<const ulonglong2*>(&vs[r][g4 + k][0]);  // LDS.128
            const u64 m = v.x;
            const u64 s = v.y;
            #pragma unroll
            for (int o = 0; o < 4; o++) {
                const int t = k - o;
                if (t >= 0 && t < 11) {
                    const u64 w2 = ldw2(t);
                    hmu[o] = fma2(m, w2, hmu[o]);
                    hsp[o] = fma2(s, w2, hsp[o]);
                }
            }
        }

        // ---- packed epilogue: 2 pixels per f32x2 op (renames are free) ----
        const u64 NEG1 = ldc2(cNEG1);
        const u64 TWOS = ldc2(cTWOS);
        const u64 SCL  = ldc2(cSCL);
        const u64 C1S  = ldc2(cC1S);
        const u64 C2S  = ldc2(cC2S);

        float nnv[4], ddv[4];
        #pragma unroll
        for (int p = 0; p < 2; p++) {
            float mu1a, mu2a, mu1b, mu2b, sqa, xya, sqb, xyb;
            unpack2(hmu[2*p    ], mu1a, mu2a);
            unpack2(hmu[2*p + 1], mu1b, mu2b);
            unpack2(hsp[2*p    ], sqa,  xya);
            unpack2(hsp[2*p + 1], sqb,  xyb);
            const u64 A   = pack2(mu1a, mu1b);    // (mu1 px0, mu1 px1)
            const u64 B   = pack2(mu2a, mu2b);
            const u64 SQS = pack2(sqa,  sqb);     // G(xx)+G(yy)
            const u64 EXY = pack2(xya,  xyb);     // G(xy)

            const u64 m12  = mul2(A, B);
            const u64 msum = fma2(B, B, mul2(A, A));
            const u64 s12  = fma2(m12,  NEG1, EXY);
            const u64 ssum = fma2(msum, NEG1, SQS);
            const u64 f1 = fma2(m12,  TWOS, C1S);
            const u64 f2 = fma2(s12,  TWOS, C2S);
            const u64 f3 = fma2(msum, SCL,  C1S);
            const u64 f4 = fma2(ssum, SCL,  C2S);
            const u64 nn2 = mul2(f1, f2);
            const u64 dd2 = mul2(f3, f4);
            unpack2(nn2, nnv[2*p], nnv[2*p + 1]);
            unpack2(dd2, ddv[2*p], ddv[2*p + 1]);
        }

        if (!interior) {   // boundary blocks only (≈2.7%): mask invalid pixels
            #pragma unroll
            for (int o = 0; o < 4; o++) {
                const bool valid = (by + r < H) && (bx + g4 + o < W);
                if (!valid) { nnv[o] = 0.f; ddv[o] = 1.f; }
            }
        }

        // sum_i n_i/d_i = (sum_i n_i * prod_{j!=i} d_j) / prod_j d_j -> one RCP / 4 px
        const float d01 = ddv[0] * ddv[1];
        const float d23 = ddv[2] * ddv[3];
        const float D   = d01 * d23;
        const float s01 = fmaf(nnv[0], ddv[1], nnv[1] * ddv[0]);
        const float s23 = fmaf(nnv[2], ddv[3], nnv[3] * ddv[2]);
        const float S   = fmaf(s01, d23, s23 * d01);
        lsum = __fdividef(S, D);
    }

    // ---------------- block reduction ----------------
    #pragma unroll
    for (int off = 16; off; off >>= 1)
        lsum += __shfl_xor_sync(0xffffffffu, lsum, off);
    if ((tid & 31) == 0) wsum[tid >> 5] = lsum;
    __syncthreads();
    if (tid == 0) {
        float s = 0.f;
        #pragma unroll
        for (int w = 0; w < NTHREADS / 32; w++) s += wsum[w];
        g_blockSums[blockIdx.y * gridDim.x + blockIdx.x] = s;
        __threadfence();
        unsigned int prev = atomicAdd(&g_count, 1u);
        isLast = (prev == (unsigned int)(nBlocks - 1));
    }
    __syncthreads();

    // ---------------- last block: final deterministic reduce ----------------
    if (isLast) {
        // reuse vs storage for the double scratch (all vs uses are done)
        double* dsm = reinterpret_cast<double*>(&vs[0][0][0]);
        double acc = 0.0;
        if ((nBlocks & 3) == 0) {
            const float4* p = (const float4*)g_blockSums;
            const int n4 = nBlocks >> 2;
            for (int i = tid; i < n4; i += NTHREADS) {
                float4 v = p[i];
                acc += (double)v.x + (double)v.y + (double)v.z + (double)v.w;
            }
        } else {
            for (int i = tid; i < nBlocks; i += NTHREADS)
                acc += (double)g_blockSums[i];
        }
        dsm[tid] = acc;
        __syncthreads();
        #pragma unroll
        for (int s = NTHREADS / 2; s; s >>= 1) {
            if (tid < s) dsm[tid] += dsm[tid + s];
            __syncthreads();
        }
        if (tid == 0) {
            out[0] = (float)(dsm[0] * inv_n);
            g_count = 0;   // reset for next graph replay (deterministic)
        }
    }
}

extern "C" void kernel_launch(void* const* d_in, const int* in_sizes, int n_in,
                              void* d_out, int out_size)
{
    (void)n_in; (void)out_size;
    const float* img1 = (const float*)d_in[0];
    const float* img2 = (const float*)d_in[1];

    const long long n = (long long)in_sizes[0];
    int W = (int)(sqrt((double)n) + 0.5);
    if (W <= 0) W = 1;
    int H = (int)(n / W);

    dim3 grid((W + TILE_W - 1) / TILE_W, (H + TILE_H - 1) / TILE_H);
    const int nb = (int)(grid.x * grid.y);
    const double inv_n = 1.0 / ((double)H * (double)W);
    ssim_tile_kernel<<<grid, NTHREADS>>>(img1, img2, W, H, nb, inv_n,
                                         (float*)d_out);
}